// round 1
// baseline (speedup 1.0000x reference)
#include <cuda_runtime.h>
#include <cuda_bf16.h>

#define N_NODES 64000
#define N_GRAPHS 128
#define D 64
#define MAX_E 1024000

// ---------------- scratch (device globals; no allocation allowed) ----------
__device__ float g_h0[N_NODES * D];
__device__ float g_h1[N_NODES * D];
__device__ float g_aggr[N_NODES * D];
__device__ int   g_deg[N_NODES];
__device__ int   g_rowptr[N_NODES + 1];
__device__ int   g_pos[N_NODES];
__device__ int   g_srcs[MAX_E];
__device__ float g_inv[N_NODES];
__device__ float g_pool[N_GRAPHS * 2];
__device__ int   g_gcnt[N_GRAPHS];
__device__ int   g_bsums[128];
__device__ int   g_is64;

__device__ __forceinline__ const float* sel_in(int s, const float* x) {
    return s == 0 ? x : (s == 1 ? g_h0 : g_h1);
}
__device__ __forceinline__ float* sel_out(int s) {
    return s == 1 ? g_h0 : g_h1;
}

// ---------------- index dtype probe --------------------------------------
// If buffer is int32, reading as int64 combines adjacent values -> almost
// surely out of [0, N_NODES). 16 consecutive in-range int64 reads => int64.
__global__ void k_detect(const void* edges) {
    if (threadIdx.x == 0 && blockIdx.x == 0) {
        const long long* p = (const long long*)edges;
        int ok = 1;
        for (int i = 0; i < 16; i++) {
            long long v = p[i];
            if (v < 0 || v >= N_NODES) ok = 0;
        }
        g_is64 = ok;
    }
}

__global__ void k_zero() {
    int i = blockIdx.x * blockDim.x + threadIdx.x;
    if (i < N_NODES) g_deg[i] = 0;
    if (i < N_GRAPHS * 2) g_pool[i] = 0.f;
    if (i < N_GRAPHS) g_gcnt[i] = 0;
}

__global__ void k_count(const void* edges, int E) {
    int e = blockIdx.x * blockDim.x + threadIdx.x;
    if (e >= E) return;
    int dst = g_is64 ? (int)((const long long*)edges)[E + e]
                     : ((const int*)edges)[E + e];
    atomicAdd(&g_deg[dst], 1);
}

__global__ void k_gcnt(const void* batch) {
    int i = blockIdx.x * blockDim.x + threadIdx.x;
    if (i >= N_NODES) return;
    int g = g_is64 ? (int)((const long long*)batch)[i]
                   : ((const int*)batch)[i];
    atomicAdd(&g_gcnt[g], 1);
}

// ---------------- 3-kernel exclusive scan of degrees ----------------------
__global__ void k_scan1() {
    __shared__ int s[512];
    int t = threadIdx.x;
    int i = blockIdx.x * 512 + t;          // 125 blocks * 512 = 64000 exactly
    int d = g_deg[i];
    s[t] = d;
    __syncthreads();
    for (int off = 1; off < 512; off <<= 1) {
        int v = (t >= off) ? s[t - off] : 0;
        __syncthreads();
        s[t] += v;
        __syncthreads();
    }
    g_rowptr[i] = s[t] - d;               // local exclusive
    if (t == 511) g_bsums[blockIdx.x] = s[511];
}

__global__ void k_scan2() {
    __shared__ int s[128];
    int t = threadIdx.x;
    int v = (t < 125) ? g_bsums[t] : 0;
    s[t] = v;
    __syncthreads();
    for (int off = 1; off < 128; off <<= 1) {
        int u = (t >= off) ? s[t - off] : 0;
        __syncthreads();
        s[t] += u;
        __syncthreads();
    }
    g_bsums[t] = s[t] - v;                // exclusive block offsets
}

__global__ void k_scan3(int E) {
    int t = threadIdx.x;
    int i = blockIdx.x * 512 + t;
    int rp = g_rowptr[i] + g_bsums[blockIdx.x];
    g_rowptr[i] = rp;
    g_pos[i] = rp;
    int d = g_deg[i];
    g_inv[i] = d > 0 ? 1.0f / (float)d : 0.f;
    if (i == 0) g_rowptr[N_NODES] = E;
}

__global__ void k_fill(const void* edges, int E) {
    int e = blockIdx.x * blockDim.x + threadIdx.x;
    if (e >= E) return;
    int src, dst;
    if (g_is64) {
        const long long* p = (const long long*)edges;
        src = (int)p[e];
        dst = (int)p[E + e];
    } else {
        const int* p = (const int*)edges;
        src = p[e];
        dst = p[E + e];
    }
    int pidx = atomicAdd(&g_pos[dst], 1);
    g_srcs[pidx] = src;
}

// ---------------- mean aggregation: warp per node, float2 lanes -----------
__global__ void k_aggregate(int in_sel, const float* __restrict__ x) {
    const float* in = sel_in(in_sel, x);
    int warp = (blockIdx.x * blockDim.x + threadIdx.x) >> 5;
    int lane = threadIdx.x & 31;
    if (warp >= N_NODES) return;
    int rs = g_rowptr[warp], re = g_rowptr[warp + 1];
    const float2* in2 = (const float2*)in;
    float2 acc = make_float2(0.f, 0.f);
    int e = rs;
    for (; e + 4 <= re; e += 4) {
        int s0 = g_srcs[e], s1 = g_srcs[e + 1], s2 = g_srcs[e + 2], s3 = g_srcs[e + 3];
        float2 v0 = in2[s0 * 32 + lane];
        float2 v1 = in2[s1 * 32 + lane];
        float2 v2 = in2[s2 * 32 + lane];
        float2 v3 = in2[s3 * 32 + lane];
        acc.x += (v0.x + v1.x) + (v2.x + v3.x);
        acc.y += (v0.y + v1.y) + (v2.y + v3.y);
    }
    for (; e < re; e++) {
        float2 v = in2[g_srcs[e] * 32 + lane];
        acc.x += v.x; acc.y += v.y;
    }
    float iv = g_inv[warp];
    ((float2*)g_aggr)[warp * 32 + lane] = make_float2(acc.x * iv, acc.y * iv);
}

// ---------------- fused dual GEMM + bias + relu ---------------------------
// out[n][j] = relu( sum_k aggr[n][k]*Wl[j][k] + h[n][k]*Wr[j][k] + b[j] )
// block = 128 threads, tile = 16 nodes x 64 outputs, thread = 2 nodes x 4 j.
#define LIN_TPB 128
__global__ void __launch_bounds__(LIN_TPB)
k_linear(int in_sel, int out_sel, const float* __restrict__ x,
         const float* __restrict__ Wl, const float* __restrict__ Wr,
         const float* __restrict__ bias, int do_relu) {
    __shared__ float wlT[64 * 64];
    __shared__ float wrT[64 * 64];
    __shared__ float sA[16 * 65];
    __shared__ float sX[16 * 65];
    const float* in = sel_in(in_sel, x);
    float* out = sel_out(out_sel);
    int t = threadIdx.x;
    for (int idx = t; idx < 4096; idx += LIN_TPB) {
        int j = idx >> 6, k = idx & 63;
        wlT[k * 64 + j] = Wl[idx];
        wrT[k * 64 + j] = Wr[idx];
    }
    int jt = t & 15;        // j group: features jt*4 .. jt*4+3
    int nt = t >> 4;        // node pair: nodes nt*2, nt*2+1
    float4 bv = *(const float4*)&bias[jt * 4];
    __syncthreads();
    const int ntiles = N_NODES / 16;   // 4000
    for (int tile = blockIdx.x; tile < ntiles; tile += gridDim.x) {
        int base = tile * 16 * 64;
        for (int idx = t; idx < 1024; idx += LIN_TPB) {
            int n = idx >> 6, k = idx & 63;
            sA[n * 65 + k] = g_aggr[base + idx];
            sX[n * 65 + k] = in[base + idx];
        }
        __syncthreads();
        float a00 = bv.x, a01 = bv.y, a02 = bv.z, a03 = bv.w;
        float a10 = bv.x, a11 = bv.y, a12 = bv.z, a13 = bv.w;
        int r0 = (nt * 2) * 65, r1 = r0 + 65;
        #pragma unroll 8
        for (int k = 0; k < 64; k++) {
            float va0 = sA[r0 + k], va1 = sA[r1 + k];
            float vx0 = sX[r0 + k], vx1 = sX[r1 + k];
            float4 wl4 = *(const float4*)&wlT[k * 64 + jt * 4];
            float4 wr4 = *(const float4*)&wrT[k * 64 + jt * 4];
            a00 += va0 * wl4.x + vx0 * wr4.x;
            a01 += va0 * wl4.y + vx0 * wr4.y;
            a02 += va0 * wl4.z + vx0 * wr4.z;
            a03 += va0 * wl4.w + vx0 * wr4.w;
            a10 += va1 * wl4.x + vx1 * wr4.x;
            a11 += va1 * wl4.y + vx1 * wr4.y;
            a12 += va1 * wl4.z + vx1 * wr4.z;
            a13 += va1 * wl4.w + vx1 * wr4.w;
        }
        if (do_relu) {
            a00 = fmaxf(a00, 0.f); a01 = fmaxf(a01, 0.f);
            a02 = fmaxf(a02, 0.f); a03 = fmaxf(a03, 0.f);
            a10 = fmaxf(a10, 0.f); a11 = fmaxf(a11, 0.f);
            a12 = fmaxf(a12, 0.f); a13 = fmaxf(a13, 0.f);
        }
        float* o = &out[(tile * 16 + nt * 2) * 64 + jt * 4];
        *(float4*)o = make_float4(a00, a01, a02, a03);
        *(float4*)(o + 64) = make_float4(a10, a11, a12, a13);
        __syncthreads();
    }
}

// ---------------- final 64->2 layer fused with graph pooling --------------
__global__ void k_final(const float* __restrict__ Wl_out,
                        const float* __restrict__ Wr_out,
                        const float* __restrict__ b_out,
                        const void* __restrict__ batch) {
    int warp = (blockIdx.x * blockDim.x + threadIdx.x) >> 5;
    int lane = threadIdx.x & 31;
    if (warp >= N_NODES) return;
    float2 a  = ((const float2*)g_aggr)[warp * 32 + lane];
    float2 xv = ((const float2*)g_h0)[warp * 32 + lane];
    float2 wl0 = ((const float2*)Wl_out)[lane];
    float2 wl1 = ((const float2*)Wl_out)[32 + lane];
    float2 wr0 = ((const float2*)Wr_out)[lane];
    float2 wr1 = ((const float2*)Wr_out)[32 + lane];
    float s0 = a.x * wl0.x + a.y * wl0.y + xv.x * wr0.x + xv.y * wr0.y;
    float s1 = a.x * wl1.x + a.y * wl1.y + xv.x * wr1.x + xv.y * wr1.y;
    #pragma unroll
    for (int off = 16; off > 0; off >>= 1) {
        s0 += __shfl_xor_sync(0xFFFFFFFFu, s0, off);
        s1 += __shfl_xor_sync(0xFFFFFFFFu, s1, off);
    }
    if (lane == 0) {
        int g = g_is64 ? (int)((const long long*)batch)[warp]
                       : ((const int*)batch)[warp];
        atomicAdd(&g_pool[g * 2 + 0], s0 + b_out[0]);
        atomicAdd(&g_pool[g * 2 + 1], s1 + b_out[1]);
    }
}

__global__ void k_pool_out(float* __restrict__ out) {
    int i = threadIdx.x;
    if (i >= N_GRAPHS * 2) return;
    int g = i >> 1;
    int c = g_gcnt[g];
    out[i] = (c > 0) ? g_pool[i] / (float)c : 0.f;
}

// ---------------- launch ---------------------------------------------------
extern "C" void kernel_launch(void* const* d_in, const int* in_sizes, int n_in,
                              void* d_out, int out_size) {
    const float* x      = (const float*)d_in[0];
    const void*  edges  = d_in[1];
    const void*  batch  = d_in[2];
    const float* Wl     = (const float*)d_in[3];
    const float* Wr     = (const float*)d_in[4];
    const float* b      = (const float*)d_in[5];
    const float* Wl_out = (const float*)d_in[6];
    const float* Wr_out = (const float*)d_in[7];
    const float* b_out  = (const float*)d_in[8];
    float* out = (float*)d_out;
    int E = in_sizes[1] / 2;

    int nb_nodes = (N_NODES + 255) / 256;     // 250
    int nb_edges = (E + 255) / 256;           // 4000
    int nb_warps = N_NODES / 8;               // 8000 (256 thr = 8 warps)

    k_detect<<<1, 32>>>(edges);
    k_zero<<<nb_nodes, 256>>>();
    k_count<<<nb_edges, 256>>>(edges, E);
    k_gcnt<<<nb_nodes, 256>>>(batch);
    k_scan1<<<125, 512>>>();
    k_scan2<<<1, 128>>>();
    k_scan3<<<125, 512>>>(E);
    k_fill<<<nb_edges, 256>>>(edges, E);

    // layer 0: in = x, out = g_h0
    k_aggregate<<<nb_warps, 256>>>(0, x);
    k_linear<<<592, LIN_TPB>>>(0, 1, x, Wl, Wr, b, 1);
    // layer 1: g_h0 -> g_h1
    k_aggregate<<<nb_warps, 256>>>(1, x);
    k_linear<<<592, LIN_TPB>>>(1, 2, x, Wl + 4096, Wr + 4096, b + 64, 1);
    // layer 2: g_h1 -> g_h0
    k_aggregate<<<nb_warps, 256>>>(2, x);
    k_linear<<<592, LIN_TPB>>>(2, 1, x, Wl + 8192, Wr + 8192, b + 128, 1);
    // final layer on g_h0 + pooling
    k_aggregate<<<nb_warps, 256>>>(1, x);
    k_final<<<nb_warps, 256>>>(Wl_out, Wr_out, b_out, batch);
    k_pool_out<<<1, 256>>>(out);
}

// round 2
// speedup vs baseline: 1.2763x; 1.2763x over previous
#include <cuda_runtime.h>
#include <cuda_bf16.h>

#define N_NODES 64000
#define N_GRAPHS 128
#define D 64
#define MAX_E 1024000

// ---------------- scratch (device globals; no allocation allowed) ----------
__device__ float g_h0[N_NODES * D];
__device__ float g_h1[N_NODES * D];
__device__ float g_aggr[N_NODES * D];
__device__ float g_y[N_NODES * 2];
__device__ int   g_deg[N_NODES];
__device__ int   g_rowptr[N_NODES + 1];
__device__ int   g_pos[N_NODES];
__device__ int   g_srcs[MAX_E];
__device__ float g_inv[N_NODES];
__device__ float g_pool[N_GRAPHS * 2];
__device__ int   g_gcnt[N_GRAPHS];
__device__ int   g_bsums[128];
__device__ int   g_is64;

__device__ __forceinline__ const float* sel_in(int s, const float* x) {
    return s == 0 ? x : (s == 1 ? g_h0 : g_h1);
}
__device__ __forceinline__ float* sel_out(int s) {
    return s == 1 ? g_h0 : g_h1;
}
__device__ __forceinline__ int load_idx(const void* p, int i) {
    return g_is64 ? (int)((const long long*)p)[i] : ((const int*)p)[i];
}

// ---------------- index dtype probe --------------------------------------
__global__ void k_detect(const void* edges) {
    if (threadIdx.x == 0 && blockIdx.x == 0) {
        const long long* p = (const long long*)edges;
        int ok = 1;
        for (int i = 0; i < 16; i++) {
            long long v = p[i];
            if (v < 0 || v >= N_NODES) ok = 0;
        }
        g_is64 = ok;
    }
}

__global__ void k_zero() {
    int i = blockIdx.x * blockDim.x + threadIdx.x;
    if (i < N_NODES) g_deg[i] = 0;
    if (i < N_GRAPHS * 2) g_pool[i] = 0.f;
    if (i < N_GRAPHS) g_gcnt[i] = 0;
}

__global__ void k_count(const void* edges, int E) {
    int e = blockIdx.x * blockDim.x + threadIdx.x;
    if (e >= E) return;
    atomicAdd(&g_deg[load_idx(edges, E + e)], 1);
}

// graph counts via per-block smem histogram (batch is sorted -> global
// atomics to one address would serialize; smem ATOMS absorbs it)
__global__ void k_gcnt(const void* batch) {
    __shared__ int h[N_GRAPHS];
    for (int i = threadIdx.x; i < N_GRAPHS; i += blockDim.x) h[i] = 0;
    __syncthreads();
    int i = blockIdx.x * blockDim.x + threadIdx.x;
    if (i < N_NODES) atomicAdd(&h[load_idx(batch, i)], 1);
    __syncthreads();
    for (int g = threadIdx.x; g < N_GRAPHS; g += blockDim.x)
        if (h[g]) atomicAdd(&g_gcnt[g], h[g]);
}

// ---------------- 3-kernel exclusive scan of degrees ----------------------
__global__ void k_scan1() {
    __shared__ int s[512];
    int t = threadIdx.x;
    int i = blockIdx.x * 512 + t;          // 125 blocks * 512 = 64000 exactly
    int d = g_deg[i];
    s[t] = d;
    __syncthreads();
    for (int off = 1; off < 512; off <<= 1) {
        int v = (t >= off) ? s[t - off] : 0;
        __syncthreads();
        s[t] += v;
        __syncthreads();
    }
    g_rowptr[i] = s[t] - d;
    if (t == 511) g_bsums[blockIdx.x] = s[511];
}

__global__ void k_scan2() {
    __shared__ int s[128];
    int t = threadIdx.x;
    int v = (t < 125) ? g_bsums[t] : 0;
    s[t] = v;
    __syncthreads();
    for (int off = 1; off < 128; off <<= 1) {
        int u = (t >= off) ? s[t - off] : 0;
        __syncthreads();
        s[t] += u;
        __syncthreads();
    }
    g_bsums[t] = s[t] - v;
}

__global__ void k_scan3(int E) {
    int t = threadIdx.x;
    int i = blockIdx.x * 512 + t;
    int rp = g_rowptr[i] + g_bsums[blockIdx.x];
    g_rowptr[i] = rp;
    g_pos[i] = rp;
    int d = g_deg[i];
    g_inv[i] = d > 0 ? 1.0f / (float)d : 0.f;
    if (i == 0) g_rowptr[N_NODES] = E;
}

__global__ void k_fill(const void* edges, int E) {
    int e = blockIdx.x * blockDim.x + threadIdx.x;
    if (e >= E) return;
    int src = load_idx(edges, e);
    int dst = load_idx(edges, E + e);
    int pidx = atomicAdd(&g_pos[dst], 1);
    g_srcs[pidx] = src;
}

// ---------------- mean aggregation: warp per node, float2 lanes -----------
__global__ void k_aggregate(int in_sel, const float* __restrict__ x) {
    const float* in = sel_in(in_sel, x);
    int warp = (blockIdx.x * blockDim.x + threadIdx.x) >> 5;
    int lane = threadIdx.x & 31;
    if (warp >= N_NODES) return;
    int rs = g_rowptr[warp], re = g_rowptr[warp + 1];
    const float2* in2 = (const float2*)in;
    float2 acc = make_float2(0.f, 0.f);
    int e = rs;
    for (; e + 8 <= re; e += 8) {
        int s0 = g_srcs[e],     s1 = g_srcs[e + 1], s2 = g_srcs[e + 2], s3 = g_srcs[e + 3];
        int s4 = g_srcs[e + 4], s5 = g_srcs[e + 5], s6 = g_srcs[e + 6], s7 = g_srcs[e + 7];
        float2 v0 = in2[s0 * 32 + lane];
        float2 v1 = in2[s1 * 32 + lane];
        float2 v2 = in2[s2 * 32 + lane];
        float2 v3 = in2[s3 * 32 + lane];
        float2 v4 = in2[s4 * 32 + lane];
        float2 v5 = in2[s5 * 32 + lane];
        float2 v6 = in2[s6 * 32 + lane];
        float2 v7 = in2[s7 * 32 + lane];
        acc.x += ((v0.x + v1.x) + (v2.x + v3.x)) + ((v4.x + v5.x) + (v6.x + v7.x));
        acc.y += ((v0.y + v1.y) + (v2.y + v3.y)) + ((v4.y + v5.y) + (v6.y + v7.y));
    }
    for (; e + 4 <= re; e += 4) {
        int s0 = g_srcs[e], s1 = g_srcs[e + 1], s2 = g_srcs[e + 2], s3 = g_srcs[e + 3];
        float2 v0 = in2[s0 * 32 + lane];
        float2 v1 = in2[s1 * 32 + lane];
        float2 v2 = in2[s2 * 32 + lane];
        float2 v3 = in2[s3 * 32 + lane];
        acc.x += (v0.x + v1.x) + (v2.x + v3.x);
        acc.y += (v0.y + v1.y) + (v2.y + v3.y);
    }
    for (; e < re; e++) {
        float2 v = in2[g_srcs[e] * 32 + lane];
        acc.x += v.x; acc.y += v.y;
    }
    float iv = g_inv[warp];
    ((float2*)g_aggr)[warp * 32 + lane] = make_float2(acc.x * iv, acc.y * iv);
}

// ---------------- fused dual GEMM + bias + relu ---------------------------
// Two passes over a 32-node tile: pass0 = aggr @ Wl^T, pass1 = in @ Wr^T,
// sharing one smem value buffer. Thread = 4 nodes x 4 j outputs.
// Per warp per k per pass: 16 FFMA-instr (8 SM-cyc) vs ~6 LDS-cyc -> FMA-bound.
#define LIN_TPB 128
__global__ void __launch_bounds__(LIN_TPB)
k_linear(int in_sel, int out_sel, const float* __restrict__ x,
         const float* __restrict__ Wl, const float* __restrict__ Wr,
         const float* __restrict__ bias, int do_relu) {
    __shared__ float wT[2][64 * 64];     // [pass][k*64 + j]
    __shared__ float sV[32 * 65];
    const float* in = sel_in(in_sel, x);
    float* out = sel_out(out_sel);
    int t = threadIdx.x;
    for (int idx = t; idx < 4096; idx += LIN_TPB) {
        int j = idx >> 6, k = idx & 63;
        wT[0][k * 64 + j] = Wl[idx];
        wT[1][k * 64 + j] = Wr[idx];
    }
    int jt = t & 15;        // 16 j-groups of 4
    int nt = t >> 4;        // 8 node-groups of 4
    float4 bv = *(const float4*)&bias[jt * 4];
    __syncthreads();
    const int ntiles = N_NODES / 32;   // 2000
    for (int tile = blockIdx.x; tile < ntiles; tile += gridDim.x) {
        int base = tile * 32 * 64;
        float acc[4][4];
        #pragma unroll
        for (int i = 0; i < 4; i++) {
            acc[i][0] = bv.x; acc[i][1] = bv.y; acc[i][2] = bv.z; acc[i][3] = bv.w;
        }
        #pragma unroll
        for (int p = 0; p < 2; p++) {
            const float* src = p ? (in + base) : (g_aggr + base);
            for (int idx = t; idx < 2048; idx += LIN_TPB)
                sV[(idx >> 6) * 65 + (idx & 63)] = src[idx];
            __syncthreads();
            const float* wp = wT[p];
            int r = nt * 4 * 65;
            #pragma unroll 16
            for (int k = 0; k < 64; k++) {
                float4 w4 = *(const float4*)&wp[k * 64 + jt * 4];
                #pragma unroll
                for (int i = 0; i < 4; i++) {
                    float v = sV[r + i * 65 + k];
                    acc[i][0] += v * w4.x;
                    acc[i][1] += v * w4.y;
                    acc[i][2] += v * w4.z;
                    acc[i][3] += v * w4.w;
                }
            }
            __syncthreads();
        }
        #pragma unroll
        for (int i = 0; i < 4; i++) {
            float4 o = make_float4(acc[i][0], acc[i][1], acc[i][2], acc[i][3]);
            if (do_relu) {
                o.x = fmaxf(o.x, 0.f); o.y = fmaxf(o.y, 0.f);
                o.z = fmaxf(o.z, 0.f); o.w = fmaxf(o.w, 0.f);
            }
            *(float4*)&out[(tile * 32 + nt * 4 + i) * 64 + jt * 4] = o;
        }
    }
}

// ---------------- final layer: project to 2 dims, THEN aggregate ----------
// out_g = mean_{i in g} [ mean_nbr(h)_i @ Wl_out^T + h_i @ Wr_out^T ] + b_out
// Aggregation commutes with the linear map: project y_i = h_i @ Wl_out^T
// first (2 floats/node), gather y over edges (8 MB instead of 262 MB).
__global__ void k_project(const float* __restrict__ Wl_out,
                          const float* __restrict__ Wr_out,
                          const void* __restrict__ batch) {
    __shared__ float sp[N_GRAPHS * 2];
    for (int i = threadIdx.x; i < N_GRAPHS * 2; i += blockDim.x) sp[i] = 0.f;
    __syncthreads();
    int warp = (blockIdx.x * blockDim.x + threadIdx.x) >> 5;
    int lane = threadIdx.x & 31;
    if (warp < N_NODES) {
        float2 h   = ((const float2*)g_h0)[warp * 32 + lane];
        float2 wl0 = ((const float2*)Wl_out)[lane];
        float2 wl1 = ((const float2*)Wl_out)[32 + lane];
        float2 wr0 = ((const float2*)Wr_out)[lane];
        float2 wr1 = ((const float2*)Wr_out)[32 + lane];
        float y0 = h.x * wl0.x + h.y * wl0.y;
        float y1 = h.x * wl1.x + h.y * wl1.y;
        float z0 = h.x * wr0.x + h.y * wr0.y;
        float z1 = h.x * wr1.x + h.y * wr1.y;
        #pragma unroll
        for (int off = 16; off > 0; off >>= 1) {
            y0 += __shfl_xor_sync(0xFFFFFFFFu, y0, off);
            y1 += __shfl_xor_sync(0xFFFFFFFFu, y1, off);
            z0 += __shfl_xor_sync(0xFFFFFFFFu, z0, off);
            z1 += __shfl_xor_sync(0xFFFFFFFFu, z1, off);
        }
        if (lane == 0) {
            ((float2*)g_y)[warp] = make_float2(y0, y1);
            int g = load_idx(batch, warp);
            atomicAdd(&sp[g * 2 + 0], z0);
            atomicAdd(&sp[g * 2 + 1], z1);
        }
    }
    __syncthreads();
    for (int i = threadIdx.x; i < N_GRAPHS * 2; i += blockDim.x)
        if (sp[i] != 0.f) atomicAdd(&g_pool[i], sp[i]);
}

// gather 2-dim y over edges; thread per node; smem-accumulated pooling
__global__ void k_gather2(const void* __restrict__ batch) {
    __shared__ float sp[N_GRAPHS * 2];
    for (int i = threadIdx.x; i < N_GRAPHS * 2; i += blockDim.x) sp[i] = 0.f;
    __syncthreads();
    int n = blockIdx.x * blockDim.x + threadIdx.x;
    if (n < N_NODES) {
        int rs = g_rowptr[n], re = g_rowptr[n + 1];
        const float2* y2 = (const float2*)g_y;
        float a0 = 0.f, a1 = 0.f, b0 = 0.f, b1 = 0.f;
        int e = rs;
        for (; e + 4 <= re; e += 4) {
            float2 v0 = y2[g_srcs[e]];
            float2 v1 = y2[g_srcs[e + 1]];
            float2 v2 = y2[g_srcs[e + 2]];
            float2 v3 = y2[g_srcs[e + 3]];
            a0 += v0.x + v1.x; b0 += v2.x + v3.x;
            a1 += v0.y + v1.y; b1 += v2.y + v3.y;
        }
        for (; e < re; e++) {
            float2 v = y2[g_srcs[e]];
            a0 += v.x; a1 += v.y;
        }
        float iv = g_inv[n];
        int g = load_idx(batch, n);
        atomicAdd(&sp[g * 2 + 0], (a0 + b0) * iv);
        atomicAdd(&sp[g * 2 + 1], (a1 + b1) * iv);
    }
    __syncthreads();
    for (int i = threadIdx.x; i < N_GRAPHS * 2; i += blockDim.x)
        if (sp[i] != 0.f) atomicAdd(&g_pool[i], sp[i]);
}

__global__ void k_pool_out(const float* __restrict__ b_out, float* __restrict__ out) {
    int i = threadIdx.x;
    if (i >= N_GRAPHS * 2) return;
    int g = i >> 1;
    int c = g_gcnt[g];
    out[i] = (c > 0 ? g_pool[i] / (float)c : 0.f) + b_out[i & 1];
}

// ---------------- launch ---------------------------------------------------
extern "C" void kernel_launch(void* const* d_in, const int* in_sizes, int n_in,
                              void* d_out, int out_size) {
    const float* x      = (const float*)d_in[0];
    const void*  edges  = d_in[1];
    const void*  batch  = d_in[2];
    const float* Wl     = (const float*)d_in[3];
    const float* Wr     = (const float*)d_in[4];
    const float* b      = (const float*)d_in[5];
    const float* Wl_out = (const float*)d_in[6];
    const float* Wr_out = (const float*)d_in[7];
    const float* b_out  = (const float*)d_in[8];
    float* out = (float*)d_out;
    int E = in_sizes[1] / 2;

    int nb_nodes = (N_NODES + 255) / 256;     // 250
    int nb_edges = (E + 255) / 256;
    int nb_warps = N_NODES / 8;               // 8000

    k_detect<<<1, 32>>>(edges);
    k_zero<<<nb_nodes, 256>>>();
    k_count<<<nb_edges, 256>>>(edges, E);
    k_gcnt<<<nb_nodes, 256>>>(batch);
    k_scan1<<<125, 512>>>();
    k_scan2<<<1, 128>>>();
    k_scan3<<<125, 512>>>(E);
    k_fill<<<nb_edges, 256>>>(edges, E);

    // layer 0: x -> g_h0
    k_aggregate<<<nb_warps, 256>>>(0, x);
    k_linear<<<740, LIN_TPB>>>(0, 1, x, Wl, Wr, b, 1);
    // layer 1: g_h0 -> g_h1
    k_aggregate<<<nb_warps, 256>>>(1, x);
    k_linear<<<740, LIN_TPB>>>(1, 2, x, Wl + 4096, Wr + 4096, b + 64, 1);
    // layer 2: g_h1 -> g_h0
    k_aggregate<<<nb_warps, 256>>>(2, x);
    k_linear<<<740, LIN_TPB>>>(2, 1, x, Wl + 8192, Wr + 8192, b + 128, 1);
    // final layer: project h to 2 dims, gather over edges, pool
    k_project<<<nb_warps, 256>>>(Wl_out, Wr_out, batch);
    k_gather2<<<nb_nodes, 256>>>(batch);
    k_pool_out<<<1, 256>>>(b_out, out);
}